// round 1
// baseline (speedup 1.0000x reference)
#include <cuda_runtime.h>
#include <cstddef>
#include <cstdint>

// Problem constants (from reference)
static constexpr int B  = 4;
static constexpr int C  = 64;
static constexpr int NX = 432;
static constexpr int NY = 496;
static constexpr long PLANE   = (long)NY * NX;          // 214272
static constexpr long PER_BIN = (long)B * C * PLANE;    // 54,853,632 floats

// ---------------------------------------------------------------------------
// Kernel 1: zero-fill the whole output with vectorized stores (grid-stride)
// ---------------------------------------------------------------------------
__global__ void zero_fill_f4(float4* __restrict__ out, size_t n4) {
    size_t i      = (size_t)blockIdx.x * blockDim.x + threadIdx.x;
    size_t stride = (size_t)gridDim.x * blockDim.x;
    const float4 z = make_float4(0.f, 0.f, 0.f, 0.f);
    for (; i < n4; i += stride) {
        out[i] = z;
    }
}

// ---------------------------------------------------------------------------
// Kernel 2: scatter all 3 bins. blockIdx.y selects the bin.
// Thread t handles (pillar p = t>>6, channel c = t&63): reads are coalesced
// (pillar features are [NP, 64] row-major), writes are scattered 4B stores.
// ---------------------------------------------------------------------------
__global__ void scatter3(const float* __restrict__ pf0, const int* __restrict__ vc0,
                         const float* __restrict__ pf1, const int* __restrict__ vc1,
                         const float* __restrict__ pf2, const int* __restrict__ vc2,
                         float* __restrict__ out, int np) {
    const int bin = blockIdx.y;
    const float* pf;
    const int*   vc;
    if (bin == 0)      { pf = pf0; vc = vc0; }
    else if (bin == 1) { pf = pf1; vc = vc1; }
    else               { pf = pf2; vc = vc2; }

    long t = (long)blockIdx.x * blockDim.x + threadIdx.x;
    long total = (long)np * C;
    if (t >= total) return;

    int p = (int)(t >> 6);     // pillar index
    int c = (int)(t & 63);     // channel

    // coords row: [b, z, y, x] as one int4 (16B aligned: row stride is 4 ints)
    int4 co = reinterpret_cast<const int4*>(vc)[p];
    // Reference flat (within sample): z + y*NX + x  (z == 0 but keep for exactness)
    long spatial = (long)co.y + (long)co.z * NX + (long)co.w;
    long off = ((long)co.x * C + c) * PLANE + spatial;

    float v = pf[t];  // coalesced read
    out[(long)bin * PER_BIN + off] = v;
}

extern "C" void kernel_launch(void* const* d_in, const int* in_sizes, int n_in,
                              void* d_out, int out_size) {
    // Input order (metadata / reference signature):
    //   0: pillar_features_bin_0 [NP, 64] f32
    //   1: voxel_coords_bin_0    [NP, 4]  i32
    //   2: pillar_features_bin_1
    //   3: voxel_coords_bin_1
    //   4: pillar_features_bin_2
    //   5: voxel_coords_bin_2
    const float* pf0 = (const float*)d_in[0];
    const int*   vc0 = (const int*)  d_in[1];
    const float* pf1 = (const float*)d_in[2];
    const int*   vc1 = (const int*)  d_in[3];
    const float* pf2 = (const float*)d_in[4];
    const int*   vc2 = (const int*)  d_in[5];
    float* out = (float*)d_out;

    const int np = in_sizes[1] / 4;  // pillars per bin (coords rows)

    // 1) Zero-fill entire output (out_size floats, divisible by 4)
    size_t n4 = (size_t)out_size / 4;
    int zthreads = 256;
    int zblocks  = 148 * 16;  // plenty of waves of MLP, grid-stride loop
    zero_fill_f4<<<zblocks, zthreads>>>((float4*)out, n4);

    // 2) Scatter all three bins (ordered after zero-fill on the same stream)
    long per_bin_threads = (long)np * C;
    int sthreads = 256;
    dim3 sgrid((unsigned)((per_bin_threads + sthreads - 1) / sthreads), 3, 1);
    scatter3<<<sgrid, sthreads>>>(pf0, vc0, pf1, vc1, pf2, vc2, out, np);
}

// round 2
// speedup vs baseline: 1.7480x; 1.7480x over previous
#include <cuda_runtime.h>
#include <cstddef>
#include <cstdint>

// Problem constants (from reference)
static constexpr int B  = 4;
static constexpr int C  = 64;
static constexpr int NX = 432;
static constexpr int NY = 496;
static constexpr int NBINS = 3;
static constexpr int  PLANE   = NY * NX;            // 214272 (divisible by 4)
static constexpr int  PLANE4  = PLANE / 4;          // 53568
static constexpr long PER_BIN = (long)B * C * PLANE;

// Inverse index map: cell -> pillar id (or -1). 3*4*214272*4B ~= 10.3 MB scratch.
__device__ int g_idx[NBINS * B * PLANE];

// ---------------------------------------------------------------------------
// Kernel 1: fill index map with -1 (vectorized). n4 = NBINS*B*PLANE/4 = 642816
// which is exactly 2511 * 256 -> no bounds check needed, but keep one anyway.
// ---------------------------------------------------------------------------
__global__ void fill_idx() {
    int i = blockIdx.x * blockDim.x + threadIdx.x;
    const int n4 = NBINS * B * PLANE / 4;
    if (i < n4) {
        reinterpret_cast<int4*>(g_idx)[i] = make_int4(-1, -1, -1, -1);
    }
}

// ---------------------------------------------------------------------------
// Kernel 2: scatter pillar indices into the map (tiny: 3*64000 4B stores)
// ---------------------------------------------------------------------------
__global__ void scatter_idx(const int* __restrict__ vc0,
                            const int* __restrict__ vc1,
                            const int* __restrict__ vc2, int np) {
    const int bin = blockIdx.y;
    const int* vc = (bin == 0) ? vc0 : (bin == 1) ? vc1 : vc2;
    int p = blockIdx.x * blockDim.x + threadIdx.x;
    if (p >= np) return;
    int4 co = reinterpret_cast<const int4*>(vc)[p];  // [b, z, y, x]
    // reference flat-in-sample: z + y*NX + x   (z == 0, kept for exactness)
    int cell = co.x * PLANE + co.y + co.z * NX + co.w;
    g_idx[bin * (B * PLANE) + cell] = p;
}

// ---------------------------------------------------------------------------
// Kernel 3: streaming gather. grid = (ceil(PLANE4/256), B*C, NBINS).
// Writes the entire output exactly once with coalesced float4 stores;
// idx map is L2-resident, feature gathers are sparse (7.5% occupancy).
// ---------------------------------------------------------------------------
__global__ void gather_out(const float* __restrict__ pf0,
                           const float* __restrict__ pf1,
                           const float* __restrict__ pf2,
                           float* __restrict__ out) {
    const int bin = blockIdx.z;
    const float* __restrict__ pf = (bin == 0) ? pf0 : (bin == 1) ? pf1 : pf2;

    const int bc = blockIdx.y;     // b*C + c
    const int b  = bc >> 6;
    const int c  = bc & 63;

    int s4 = blockIdx.x * blockDim.x + threadIdx.x;
    if (s4 >= PLANE4) return;

    const int4 idx = reinterpret_cast<const int4*>(
        g_idx + (size_t)(bin * B + b) * PLANE)[s4];

    float4 v;
    v.x = (idx.x >= 0) ? __ldg(pf + ((long)idx.x << 6) + c) : 0.0f;
    v.y = (idx.y >= 0) ? __ldg(pf + ((long)idx.y << 6) + c) : 0.0f;
    v.z = (idx.z >= 0) ? __ldg(pf + ((long)idx.z << 6) + c) : 0.0f;
    v.w = (idx.w >= 0) ? __ldg(pf + ((long)idx.w << 6) + c) : 0.0f;

    reinterpret_cast<float4*>(out + (long)bin * PER_BIN + (long)bc * PLANE)[s4] = v;
}

extern "C" void kernel_launch(void* const* d_in, const int* in_sizes, int n_in,
                              void* d_out, int out_size) {
    const float* pf0 = (const float*)d_in[0];
    const int*   vc0 = (const int*)  d_in[1];
    const float* pf1 = (const float*)d_in[2];
    const int*   vc1 = (const int*)  d_in[3];
    const float* pf2 = (const float*)d_in[4];
    const int*   vc2 = (const int*)  d_in[5];
    float* out = (float*)d_out;

    const int np = in_sizes[1] / 4;  // pillars per bin

    // 1) idx map := -1
    {
        const int n4 = NBINS * B * PLANE / 4;
        fill_idx<<<(n4 + 255) / 256, 256>>>();
    }

    // 2) scatter pillar ids into idx map
    {
        dim3 grid((np + 255) / 256, NBINS, 1);
        scatter_idx<<<grid, 256>>>(vc0, vc1, vc2, np);
    }

    // 3) streaming gather -> output (writes everything, including zeros)
    {
        dim3 grid((PLANE4 + 255) / 256, B * C, NBINS);
        gather_out<<<grid, 256>>>(pf0, pf1, pf2, out);
    }
}

// round 3
// speedup vs baseline: 3.4997x; 2.0021x over previous
#include <cuda_runtime.h>
#include <cstddef>
#include <cstdint>

// Problem constants (from reference)
static constexpr int B  = 4;
static constexpr int C  = 64;
static constexpr int NX = 432;
static constexpr int NY = 496;
static constexpr int NBINS = 3;
static constexpr int  PLANE   = NY * NX;            // 214272
static constexpr int  PLANE4  = PLANE / 4;          // 53568
static constexpr long PER_BIN = (long)B * C * PLANE;

// Inverse index map: cell -> global pillar row (or -1). ~10.3 MB scratch.
__device__ int g_idx[NBINS * B * PLANE];

// ---------------------------------------------------------------------------
// Kernel 1: fill index map with -1 (vectorized int4 stores)
// ---------------------------------------------------------------------------
__global__ void fill_idx() {
    int i = blockIdx.x * blockDim.x + threadIdx.x;
    const int n4 = NBINS * B * PLANE / 4;
    if (i < n4) {
        reinterpret_cast<int4*>(g_idx)[i] = make_int4(-1, -1, -1, -1);
    }
}

// ---------------------------------------------------------------------------
// Kernel 2: scatter pillar row-ids into the map (tiny)
// ---------------------------------------------------------------------------
__global__ void scatter_idx(const int* __restrict__ vc0,
                            const int* __restrict__ vc1,
                            const int* __restrict__ vc2, int np) {
    const int bin = blockIdx.y;
    const int* vc = (bin == 0) ? vc0 : (bin == 1) ? vc1 : vc2;
    int p = blockIdx.x * blockDim.x + threadIdx.x;
    if (p >= np) return;
    int4 co = reinterpret_cast<const int4*>(vc)[p];  // [b, z, y, x]
    // reference flat-in-sample: z + y*NX + x   (z == 0, kept for exactness)
    int cell = co.x * PLANE + co.y + co.z * NX + co.w;
    g_idx[bin * (B * PLANE) + cell] = p;
}

// ---------------------------------------------------------------------------
// Kernel 3: streaming gather, channel-loop layout.
// Thread owns 4 consecutive cells; loads their idx ONCE into registers, then
// loops over all 64 channels. Gather loads for a cell walk its contiguous
// 256B feature row -> near-perfect L1 sector reuse. Output stores are
// coalesced float4 with streaming hint (.cs) to keep features L2-resident.
// grid = (ceil(PLANE4/256), B, NBINS)
// ---------------------------------------------------------------------------
__global__ void gather_out(const float* __restrict__ pf0,
                           const float* __restrict__ pf1,
                           const float* __restrict__ pf2,
                           float* __restrict__ out) {
    const int bin = blockIdx.z;
    const float* __restrict__ pf = (bin == 0) ? pf0 : (bin == 1) ? pf1 : pf2;
    const int b = blockIdx.y;

    int s4 = blockIdx.x * blockDim.x + threadIdx.x;
    if (s4 >= PLANE4) return;

    const int4 idx = reinterpret_cast<const int4*>(
        g_idx + (size_t)(bin * B + b) * PLANE)[s4];

    // Feature row base offsets (global row id * 64 channels); <=4.1M, fits int.
    const int o0 = idx.x << 6, o1 = idx.y << 6, o2 = idx.z << 6, o3 = idx.w << 6;

    float* dst = out + (long)bin * PER_BIN + (long)b * C * PLANE + ((long)s4 << 2);

    #pragma unroll 8
    for (int c = 0; c < C; ++c) {
        float4 v;
        v.x = (idx.x >= 0) ? __ldg(pf + o0 + c) : 0.0f;
        v.y = (idx.y >= 0) ? __ldg(pf + o1 + c) : 0.0f;
        v.z = (idx.z >= 0) ? __ldg(pf + o2 + c) : 0.0f;
        v.w = (idx.w >= 0) ? __ldg(pf + o3 + c) : 0.0f;
        __stcs(reinterpret_cast<float4*>(dst), v);   // streaming store
        dst += PLANE;
    }
}

extern "C" void kernel_launch(void* const* d_in, const int* in_sizes, int n_in,
                              void* d_out, int out_size) {
    const float* pf0 = (const float*)d_in[0];
    const int*   vc0 = (const int*)  d_in[1];
    const float* pf1 = (const float*)d_in[2];
    const int*   vc1 = (const int*)  d_in[3];
    const float* pf2 = (const float*)d_in[4];
    const int*   vc2 = (const int*)  d_in[5];
    float* out = (float*)d_out;

    const int np = in_sizes[1] / 4;  // pillars per bin

    // 1) idx map := -1
    {
        const int n4 = NBINS * B * PLANE / 4;
        fill_idx<<<(n4 + 255) / 256, 256>>>();
    }

    // 2) scatter pillar ids into idx map
    {
        dim3 grid((np + 255) / 256, NBINS, 1);
        scatter_idx<<<grid, 256>>>(vc0, vc1, vc2, np);
    }

    // 3) streaming gather -> output (writes everything, including zeros)
    {
        dim3 grid((PLANE4 + 255) / 256, B, NBINS);
        gather_out<<<grid, 256>>>(pf0, pf1, pf2, out);
    }
}